// round 10
// baseline (speedup 1.0000x reference)
#include <cuda_runtime.h>
#include <cuda_bf16.h>
#include <cstdint>

#define B_BATCH 4
#define SEQ     2048
#define HDIM    1024
#define MTOT    (B_BATCH * SEQ)

typedef __nv_bfloat16 bf16;

// ---------------------------------------------------------------------------
// Scratch (allocation-free rule: __device__ globals). All GEMM operands live
// as bf16 hi/lo planes (hi = rn(x), lo = rn(x - hi)): same bytes as fp32.
// ---------------------------------------------------------------------------
__device__ bf16  g_x_hi   [(size_t)MTOT * HDIM];
__device__ bf16  g_x_lo   [(size_t)MTOT * HDIM];
__device__ bf16  g_win_hi [(size_t)3 * HDIM * HDIM];
__device__ bf16  g_win_lo [(size_t)3 * HDIM * HDIM];
__device__ bf16  g_wout_hi[(size_t)HDIM * HDIM];
__device__ bf16  g_wout_lo[(size_t)HDIM * HDIM];
__device__ bf16  g_qkv_hi [(size_t)MTOT * 3 * HDIM];
__device__ bf16  g_qkv_lo [(size_t)MTOT * 3 * HDIM];
__device__ float g_scores [(size_t)B_BATCH * SEQ * SEQ];
__device__ bf16  g_attn_hi[(size_t)B_BATCH * SEQ * SEQ];
__device__ bf16  g_attn_lo[(size_t)B_BATCH * SEQ * SEQ];
__device__ bf16  g_vt_hi  [(size_t)B_BATCH * HDIM * SEQ];
__device__ bf16  g_vt_lo  [(size_t)B_BATCH * HDIM * SEQ];
__device__ bf16  g_ctx_hi [(size_t)MTOT * HDIM];
__device__ bf16  g_ctx_lo [(size_t)MTOT * HDIM];

// ===========================================================================
// Base-ISA primitives (compute_103-safe): ldmatrix + mma.sync + cp.async
// ===========================================================================
__device__ __forceinline__ uint32_t smem_to_u32(const void* p) {
    uint32_t a;
    asm("{ .reg .u64 t; cvta.to.shared.u64 t, %1; cvt.u32.u64 %0, t; }"
        : "=r"(a) : "l"(p));
    return a;
}

__device__ __forceinline__ void ldmatrix_x4(uint32_t* r, uint32_t addr) {
    asm volatile("ldmatrix.sync.aligned.m8n8.x4.shared.b16 {%0,%1,%2,%3}, [%4];"
        : "=r"(r[0]), "=r"(r[1]), "=r"(r[2]), "=r"(r[3]) : "r"(addr));
}

__device__ __forceinline__ void mma_bf16(float* c, const uint32_t* a,
                                         const uint32_t* b) {
    asm volatile(
        "mma.sync.aligned.m16n8k16.row.col.f32.bf16.bf16.f32 "
        "{%0,%1,%2,%3}, {%4,%5,%6,%7}, {%8,%9}, {%0,%1,%2,%3};"
        : "+f"(c[0]), "+f"(c[1]), "+f"(c[2]), "+f"(c[3])
        : "r"(a[0]), "r"(a[1]), "r"(a[2]), "r"(a[3]), "r"(b[0]), "r"(b[1]));
}

__device__ __forceinline__ void cp_async16(uint32_t dst, const void* src) {
    asm volatile("cp.async.cg.shared.global [%0], [%1], 16;"
        :: "r"(dst), "l"(src) : "memory");
}
#define CP_COMMIT() asm volatile("cp.async.commit_group;" ::: "memory")
#define CP_WAIT2()  asm volatile("cp.async.wait_group 2;"  ::: "memory")

__device__ __forceinline__ void split2(float x, float y, uint32_t& hi, uint32_t& lo) {
    __nv_bfloat162 h = __floats2bfloat162_rn(x, y);
    __nv_bfloat162 l = __floats2bfloat162_rn(x - __bfloat162float(h.x),
                                             y - __bfloat162float(h.y));
    hi = *reinterpret_cast<const unsigned*>(&h);
    lo = *reinterpret_cast<const unsigned*>(&l);
}

// ===========================================================================
// Persistent HMMA GEMM, bf16-plane operands:
//   C[M,N] = (Ah+Al)[M,K] @ (Bh+Bl)[N,K]^T  (3-MMA split hh+hl+lh, fp32 acc)
// CTA tile 128x256, 8 warps (2x4, 64x64 each), K-chunk 32, SW64 swizzle.
// Grid = 148 persistent CTAs; each walks jobs {bid, bid+148, ...} and streams
// ALL its k-chunks through one flat 4-stage cp.async ring, so the pipeline
// stays warm across tile boundaries (epilogue overlaps next tile's loads).
// Requires M%128==0, N%256==0, K%32==0, K/32 power of two.
// ===========================================================================
// Per stage: Ahi 8K @0, Alo 8K @8192, Bhi 16K @16384, Blo 16K @32768
#define STG_BYTES 49152
#define STAGES    4
#define SMEM_TOTAL (STAGES * STG_BYTES)   // 192 KB
#define GRID_P    148

extern __shared__ __align__(1024) char dynsmem[];

template<bool WRITE_F32, bool WRITE_HILO>
__global__ void __launch_bounds__(256, 1)
tc_gemm(const bf16* __restrict__ Ah, const bf16* __restrict__ Al,
        int lda, long long sA,
        const bf16* __restrict__ Bh, const bf16* __restrict__ Bl,
        int ldb, long long sB,
        float* __restrict__ C, bf16* __restrict__ Ch, bf16* __restrict__ Cl,
        int ldc, long long sC,
        int K, const float* __restrict__ bias,
        int nx, int ny, int nJobs)
{
    const uint32_t sbase = smem_to_u32(dynsmem);
    const int tid = threadIdx.x;
    const int wid = tid >> 5;
    const int lid = tid & 31;
    const int warpM = (wid >> 2) * 64;           // 0 or 64 (rows)
    const int warpNc = (wid & 3) * 64;           // 0..192 (cols)
    const uint32_t aWarp = (uint32_t)((wid >> 2) * 4096);  // 64 rows * 64B
    const uint32_t bWarp = (uint32_t)((wid & 3) * 4096);   // 64 rows * 64B

    const int T = K >> 5;                        // chunks per job (pow2)
    const int log2T = 31 - __clz(T);
    const int bid = blockIdx.x;
    if (bid >= nJobs) return;
    const int myJobs = (nJobs - 1 - bid) / gridDim.x + 1;
    const long long totalChunks = (long long)myJobs * T;

    // ---- producer: cp.async one flat chunk into ring buffer flat&3 ----
    const int pr   = tid >> 2;           // 0..63 row base
    const int pc16 = (tid & 3) * 16;     // byte chunk within 64B row
    auto issue_flat = [&](long long flat) {
        const int jj  = (int)(flat >> log2T);
        const int kt  = (int)(flat & (T - 1));
        const int job = bid + jj * (int)gridDim.x;
        const int jx  = job % nx;
        const int jr  = job / nx;
        const int jy  = jr % ny;
        const int jz  = jr / ny;
        const long long zA = (long long)jz * sA + (long long)jy * 128 * lda;
        const long long zB = (long long)jz * sB + (long long)jx * 256 * ldb;
        const bf16* Ahb = Ah + zA;
        const bf16* Alb = Al + zA;
        const bf16* Bhb = Bh + zB;
        const bf16* Blb = Bl + zB;
        const int k0 = kt << 5;
        const uint32_t buf = sbase + (uint32_t)((int)(flat & 3)) * STG_BYTES;
        const uint32_t off0 = (uint32_t)(pr * 64 + pc16);
#pragma unroll
        for (int i = 0; i < 2; i++) {    // A planes: 128 rows
            const int row = i * 64 + pr;
            const uint32_t off = off0 + (uint32_t)(i * 4096);
            const uint32_t sw  = off ^ ((off >> 3) & 0x30u);
            cp_async16(buf +        sw, (const char*)(Ahb + (long long)row * lda + k0) + pc16);
            cp_async16(buf + 8192 + sw, (const char*)(Alb + (long long)row * lda + k0) + pc16);
        }
#pragma unroll
        for (int i = 0; i < 4; i++) {    // B planes: 256 rows
            const int row = i * 64 + pr;
            const uint32_t off = off0 + (uint32_t)(i * 4096);
            const uint32_t sw  = off ^ ((off >> 3) & 0x30u);
            cp_async16(buf + 16384 + sw, (const char*)(Bhb + (long long)row * ldb + k0) + pc16);
            cp_async16(buf + 32768 + sw, (const char*)(Blb + (long long)row * ldb + k0) + pc16);
        }
    };

    // ---- consumer lane addressing (bench-verified R7-R9) ----
    const uint32_t aOff = (uint32_t)((lid & 7) * 64 + ((lid >> 3) & 1) * 512 + (lid >> 4) * 16);
    const uint32_t aMsk = (aOff >> 3) & 0x30u;
    const uint32_t aSw0 = aOff ^ aMsk;
    const uint32_t aSw1 = (aOff | 32u) ^ aMsk;
    const uint32_t bOff = (uint32_t)((lid & 7) * 64 + ((lid >> 4) & 1) * 512 + ((lid >> 3) & 1) * 16);
    const uint32_t bMsk = (bOff >> 3) & 0x30u;
    const uint32_t bSw0 = bOff ^ bMsk;
    const uint32_t bSw1 = (bOff | 32u) ^ bMsk;

    // ---- prologue: 3 flat chunks in flight ----
#pragma unroll
    for (int s = 0; s < STAGES - 1; s++) {
        if (s < totalChunks) issue_flat(s);
        CP_COMMIT();
    }

    long long flat = 0;
    for (int j = 0; j < myJobs; j++) {
        const int job = bid + j * (int)gridDim.x;
        const int jx  = job % nx;
        const int jr  = job / nx;
        const int jy  = jr % ny;
        const int jz  = jr / ny;

        float acc[4][8][4];
#pragma unroll
        for (int i = 0; i < 4; i++)
#pragma unroll
            for (int n = 0; n < 8; n++)
#pragma unroll
                for (int k = 0; k < 4; k++) acc[i][n][k] = 0.0f;

        for (int kt = 0; kt < T; kt++, flat++) {
            CP_WAIT2();                  // flat chunk landed
            __syncthreads();             // all warps done with buffer flat-1
            if (flat + 3 < totalChunks) issue_flat(flat + 3);
            CP_COMMIT();                 // exactly one group per iteration

            const uint32_t stb = sbase + (uint32_t)(kt & 3) * STG_BYTES;
#pragma unroll
            for (int ks = 0; ks < 2; ks++) {
                const uint32_t asw = ks ? aSw1 : aSw0;
                const uint32_t bsw = ks ? bSw1 : bSw0;

                uint32_t ah[4][4], al[4][4];
#pragma unroll
                for (int mb = 0; mb < 4; mb++) {
                    const uint32_t ad = stb + aWarp + (uint32_t)(mb * 1024) + asw;
                    ldmatrix_x4(ah[mb], ad);
                    ldmatrix_x4(al[mb], ad + 8192u);
                }
#pragma unroll
                for (int p = 0; p < 4; p++) {        // 16 N-rows per p
                    uint32_t bh4[4], bl4[4];
                    const uint32_t bd = stb + 16384u + bWarp + (uint32_t)(p * 1024) + bsw;
                    ldmatrix_x4(bh4, bd);
                    ldmatrix_x4(bl4, bd + 16384u);
                    // term-batched: same-acc MMAs spaced 8 apart
#pragma unroll
                    for (int mb = 0; mb < 4; mb++)
#pragma unroll
                        for (int q = 0; q < 2; q++)
                            mma_bf16(acc[mb][p * 2 + q], ah[mb], &bh4[q * 2]); // hi*hi
#pragma unroll
                    for (int mb = 0; mb < 4; mb++)
#pragma unroll
                        for (int q = 0; q < 2; q++)
                            mma_bf16(acc[mb][p * 2 + q], ah[mb], &bl4[q * 2]); // hi*lo
#pragma unroll
                    for (int mb = 0; mb < 4; mb++)
#pragma unroll
                        for (int q = 0; q < 2; q++)
                            mma_bf16(acc[mb][p * 2 + q], al[mb], &bh4[q * 2]); // lo*hi
                }
            }
        }

        // ---- epilogue (overlaps next job's in-flight cp.async) ----
        const long long cbase = (long long)jz * sC
                              + (long long)jy * 128 * ldc + (long long)jx * 256;
#pragma unroll
        for (int mb = 0; mb < 4; mb++) {
            const int r0 = warpM + mb * 16 + (lid >> 2);
#pragma unroll
            for (int nb = 0; nb < 8; nb++) {
                const int c0 = warpNc + nb * 8 + (lid & 3) * 2;
                float b0 = 0.0f, b1 = 0.0f;
                if (bias) {
                    const float* bp = bias + jx * 256 + c0;
                    b0 = bp[0]; b1 = bp[1];
                }
                const float v00 = acc[mb][nb][0] + b0, v01 = acc[mb][nb][1] + b1;
                const float v10 = acc[mb][nb][2] + b0, v11 = acc[mb][nb][3] + b1;
                const long long o0 = cbase + (long long)r0 * ldc + c0;
                const long long o1 = o0 + (long long)8 * ldc;
                if (WRITE_F32) {
                    *(float2*)(C + o0) = make_float2(v00, v01);
                    *(float2*)(C + o1) = make_float2(v10, v11);
                }
                if (WRITE_HILO) {
                    uint32_t h, l;
                    split2(v00, v01, h, l);
                    *(uint32_t*)(Ch + o0) = h;
                    *(uint32_t*)(Cl + o0) = l;
                    split2(v10, v11, h, l);
                    *(uint32_t*)(Ch + o1) = h;
                    *(uint32_t*)(Cl + o1) = l;
                }
            }
        }
    }
}

// ===========================================================================
// fp32 -> bf16 hi/lo plane split (for X, W_in, W_out). 4 elems/thread.
// ===========================================================================
__global__ __launch_bounds__(256)
void split_f32(const float* __restrict__ x, bf16* __restrict__ hi,
               bf16* __restrict__ lo, long long n4)
{
    const long long i = (long long)blockIdx.x * 256 + threadIdx.x;
    if (i >= n4) return;
    const float4 v = ((const float4*)x)[i];
    uint32_t h0, l0, h1, l1;
    split2(v.x, v.y, h0, l0);
    split2(v.z, v.w, h1, l1);
    ((uint2*)hi)[i] = make_uint2(h0, h1);
    ((uint2*)lo)[i] = make_uint2(l0, l1);
}

// ===========================================================================
// V transpose on hi/lo planes: vt[b][d][s] = V[b][s][d]; hi,lo packed u32.
// ===========================================================================
__global__ __launch_bounds__(256)
void transpose_v(const bf16* __restrict__ qh, const bf16* __restrict__ ql,
                 bf16* __restrict__ vth, bf16* __restrict__ vtl)
{
    __shared__ uint32_t t[32][33];
    const int s0 = blockIdx.x * 32;
    const int d0 = blockIdx.y * 32;
    const int b  = blockIdx.z;
    const int tx = threadIdx.x, ty = threadIdx.y;

    const long long vb = (long long)b * SEQ * 3 * HDIM + 2 * HDIM;
#pragma unroll
    for (int j = 0; j < 4; j++) {
        const long long idx = vb + (long long)(s0 + ty + j * 8) * (3 * HDIM) + d0 + tx;
        const uint32_t h = *(const unsigned short*)(qh + idx);
        const uint32_t l = *(const unsigned short*)(ql + idx);
        t[ty + j * 8][tx] = h | (l << 16);
    }
    __syncthreads();

    const long long ob = (long long)b * HDIM * SEQ;
#pragma unroll
    for (int j = 0; j < 4; j++) {
        const long long idx = ob + (long long)(d0 + ty + j * 8) * SEQ + s0 + tx;
        const uint32_t v = t[tx][ty + j * 8];
        *(unsigned short*)(vth + idx) = (unsigned short)(v & 0xffffu);
        *(unsigned short*)(vtl + idx) = (unsigned short)(v >> 16);
    }
}

// ===========================================================================
// Softmax: reads fp32 scores + mask (applied BEFORE /sqrt(DIM)), writes
// attn probability hi/lo bf16 planes.
// ===========================================================================
__global__ __launch_bounds__(256)
void softmax_kernel(const float* __restrict__ scores, const int* __restrict__ mask,
                    bf16* __restrict__ ah, bf16* __restrict__ al)
{
    const long long row = blockIdx.x;
    const int b = (int)(row / SEQ);
    const float* p = scores + row * SEQ;
    const int* mrow = mask + (long long)b * SEQ;
    const int t = threadIdx.x;

    float v[8];
    float mx = -3.402823466e38f;
#pragma unroll
    for (int j = 0; j < 8; j++) {
        int c = t + j * 256;
        float s = p[c];
        if (mrow[c] == 0) s = -1e20f;
        s *= 0.03125f;                 // 1/sqrt(1024)
        v[j] = s;
        mx = fmaxf(mx, s);
    }

    __shared__ float redmax[8];
    __shared__ float redsum[8];

#pragma unroll
    for (int o = 16; o > 0; o >>= 1)
        mx = fmaxf(mx, __shfl_xor_sync(0xffffffffu, mx, o));
    if ((t & 31) == 0) redmax[t >> 5] = mx;
    __syncthreads();
    mx = redmax[0];
#pragma unroll
    for (int w = 1; w < 8; w++) mx = fmaxf(mx, redmax[w]);

    float sum = 0.0f;
#pragma unroll
    for (int j = 0; j < 8; j++) {
        v[j] = __expf(v[j] - mx);
        sum += v[j];
    }
#pragma unroll
    for (int o = 16; o > 0; o >>= 1)
        sum += __shfl_xor_sync(0xffffffffu, sum, o);
    if ((t & 31) == 0) redsum[t >> 5] = sum;
    __syncthreads();
    sum = 0.0f;
#pragma unroll
    for (int w = 0; w < 8; w++) sum += redsum[w];

    const float inv = 1.0f / sum;
    bf16* ph = ah + row * SEQ;
    bf16* pl = al + row * SEQ;
#pragma unroll
    for (int j = 0; j < 8; j++) {
        const int c = t + j * 256;
        const float r = v[j] * inv;
        const bf16 h = __float2bfloat16_rn(r);
        ph[c] = h;
        pl[c] = __float2bfloat16_rn(r - __bfloat162float(h));
    }
}

// ===========================================================================
// Launch
// ===========================================================================
extern "C" void kernel_launch(void* const* d_in, const int* in_sizes, int n_in,
                              void* d_out, int out_size)
{
    const float* X     = (const float*)d_in[0];
    const int*   mask  = (const int*)  d_in[1];
    const float* W_in  = (const float*)d_in[2];
    const float* b_in  = (const float*)d_in[3];
    const float* W_out = (const float*)d_in[4];
    const float* b_out = (const float*)d_in[5];
    float*       Y     = (float*)d_out;

    bf16 *xh, *xl, *wih, *wil, *woh, *wol, *qh, *ql, *ath, *atl, *vth, *vtl, *ch, *cl;
    float* sc;
    cudaGetSymbolAddress((void**)&xh,  g_x_hi);
    cudaGetSymbolAddress((void**)&xl,  g_x_lo);
    cudaGetSymbolAddress((void**)&wih, g_win_hi);
    cudaGetSymbolAddress((void**)&wil, g_win_lo);
    cudaGetSymbolAddress((void**)&woh, g_wout_hi);
    cudaGetSymbolAddress((void**)&wol, g_wout_lo);
    cudaGetSymbolAddress((void**)&qh,  g_qkv_hi);
    cudaGetSymbolAddress((void**)&ql,  g_qkv_lo);
    cudaGetSymbolAddress((void**)&sc,  g_scores);
    cudaGetSymbolAddress((void**)&ath, g_attn_hi);
    cudaGetSymbolAddress((void**)&atl, g_attn_lo);
    cudaGetSymbolAddress((void**)&vth, g_vt_hi);
    cudaGetSymbolAddress((void**)&vtl, g_vt_lo);
    cudaGetSymbolAddress((void**)&ch,  g_ctx_hi);
    cudaGetSymbolAddress((void**)&cl,  g_ctx_lo);

    cudaFuncSetAttribute(tc_gemm<false, true>,
                         cudaFuncAttributeMaxDynamicSharedMemorySize, SMEM_TOTAL);
    cudaFuncSetAttribute(tc_gemm<true, false>,
                         cudaFuncAttributeMaxDynamicSharedMemorySize, SMEM_TOTAL);

    dim3 blk(256);

    // 0. operand splits
    split_f32<<<(unsigned)((size_t)MTOT * HDIM / 4 / 256), blk>>>(X, xh, xl,
        (long long)MTOT * HDIM / 4);
    split_f32<<<(unsigned)((size_t)3 * HDIM * HDIM / 4 / 256), blk>>>(W_in, wih, wil,
        (long long)3 * HDIM * HDIM / 4);
    split_f32<<<(unsigned)((size_t)HDIM * HDIM / 4 / 256), blk>>>(W_out, woh, wol,
        (long long)HDIM * HDIM / 4);

    // 1. qkv = X @ W_in^T + b_in  -> hi/lo planes   [8192,3072], K=1024
    //    jobs: nx=12 (N/256), ny=64 (M/128), nz=1 -> 768
    tc_gemm<false, true><<<GRID_P, blk, SMEM_TOTAL>>>(
        xh, xl, HDIM, 0,
        wih, wil, HDIM, 0,
        nullptr, qh, ql, 3 * HDIM, 0,
        HDIM, b_in, 12, 64, 768);

    // 2. V^T planes
    transpose_v<<<dim3(SEQ / 32, HDIM / 32, B_BATCH), dim3(32, 8)>>>(qh, ql, vth, vtl);

    // 3. scores[b] = Q[b] @ K[b]^T -> fp32   [2048,2048] x4, K=1024
    //    jobs: nx=8, ny=16, nz=4 -> 512
    tc_gemm<true, false><<<GRID_P, blk, SMEM_TOTAL>>>(
        qh,        ql,        3 * HDIM, (long long)SEQ * 3 * HDIM,
        qh + HDIM, ql + HDIM, 3 * HDIM, (long long)SEQ * 3 * HDIM,
        sc, nullptr, nullptr, SEQ, (long long)SEQ * SEQ,
        HDIM, nullptr, 8, 16, 512);

    // 4. softmax -> attn hi/lo planes
    softmax_kernel<<<B_BATCH * SEQ, blk>>>(sc, mask, ath, atl);

    // 5. ctx[b] = attn[b] @ (V^T[b])^T -> hi/lo planes   [2048,1024] x4, K=2048
    //    jobs: nx=4, ny=16, nz=4 -> 256
    tc_gemm<false, true><<<GRID_P, blk, SMEM_TOTAL>>>(
        ath, atl, SEQ, (long long)SEQ * SEQ,
        vth, vtl, SEQ, (long long)HDIM * SEQ,
        nullptr, ch, cl, HDIM, (long long)SEQ * HDIM,
        SEQ, nullptr, 4, 16, 256);

    // 6. Y = ctx @ W_out^T + b_out -> fp32   [8192,1024], K=1024
    //    jobs: nx=4, ny=64, nz=1 -> 256
    tc_gemm<true, false><<<GRID_P, blk, SMEM_TOTAL>>>(
        ch, cl, HDIM, 0,
        woh, wol, HDIM, 0,
        Y, nullptr, nullptr, HDIM, 0,
        HDIM, b_out, 4, 64, 256);
}

// round 12
// speedup vs baseline: 1.0804x; 1.0804x over previous
#include <cuda_runtime.h>
#include <cuda_bf16.h>
#include <cstdint>

#define B_BATCH 4
#define SEQ     2048
#define HDIM    1024
#define MTOT    (B_BATCH * SEQ)

typedef __nv_bfloat16 bf16;

// ---------------------------------------------------------------------------
// Scratch (allocation-free rule: __device__ globals). All GEMM operands live
// as bf16 hi/lo planes (hi = rn(x), lo = rn(x - hi)): same bytes as fp32.
// ---------------------------------------------------------------------------
__device__ bf16  g_x_hi   [(size_t)MTOT * HDIM];
__device__ bf16  g_x_lo   [(size_t)MTOT * HDIM];
__device__ bf16  g_win_hi [(size_t)3 * HDIM * HDIM];
__device__ bf16  g_win_lo [(size_t)3 * HDIM * HDIM];
__device__ bf16  g_wout_hi[(size_t)HDIM * HDIM];
__device__ bf16  g_wout_lo[(size_t)HDIM * HDIM];
__device__ bf16  g_qkv_hi [(size_t)MTOT * 3 * HDIM];
__device__ bf16  g_qkv_lo [(size_t)MTOT * 3 * HDIM];
__device__ float g_scores [(size_t)B_BATCH * SEQ * SEQ];
__device__ bf16  g_attn_hi[(size_t)B_BATCH * SEQ * SEQ];
__device__ bf16  g_attn_lo[(size_t)B_BATCH * SEQ * SEQ];
__device__ bf16  g_vt_hi  [(size_t)B_BATCH * HDIM * SEQ];
__device__ bf16  g_vt_lo  [(size_t)B_BATCH * HDIM * SEQ];
__device__ bf16  g_ctx_hi [(size_t)MTOT * HDIM];
__device__ bf16  g_ctx_lo [(size_t)MTOT * HDIM];

// ===========================================================================
// Base-ISA primitives (compute_103-safe): ldmatrix + mma.sync + cp.async
// ===========================================================================
__device__ __forceinline__ uint32_t smem_to_u32(const void* p) {
    uint32_t a;
    asm("{ .reg .u64 t; cvta.to.shared.u64 t, %1; cvt.u32.u64 %0, t; }"
        : "=r"(a) : "l"(p));
    return a;
}

__device__ __forceinline__ void ldmatrix_x4(uint32_t* r, uint32_t addr) {
    asm volatile("ldmatrix.sync.aligned.m8n8.x4.shared.b16 {%0,%1,%2,%3}, [%4];"
        : "=r"(r[0]), "=r"(r[1]), "=r"(r[2]), "=r"(r[3]) : "r"(addr));
}

__device__ __forceinline__ void mma_bf16(float* c, const uint32_t* a,
                                         const uint32_t* b) {
    asm volatile(
        "mma.sync.aligned.m16n8k16.row.col.f32.bf16.bf16.f32 "
        "{%0,%1,%2,%3}, {%4,%5,%6,%7}, {%8,%9}, {%0,%1,%2,%3};"
        : "+f"(c[0]), "+f"(c[1]), "+f"(c[2]), "+f"(c[3])
        : "r"(a[0]), "r"(a[1]), "r"(a[2]), "r"(a[3]), "r"(b[0]), "r"(b[1]));
}

__device__ __forceinline__ void cp_async16(uint32_t dst, const void* src) {
    asm volatile("cp.async.cg.shared.global [%0], [%1], 16;"
        :: "r"(dst), "l"(src) : "memory");
}
#define CP_COMMIT() asm volatile("cp.async.commit_group;" ::: "memory")
#define CP_WAIT0()  asm volatile("cp.async.wait_group 0;"  ::: "memory")

__device__ __forceinline__ void split2(float x, float y, uint32_t& hi, uint32_t& lo) {
    __nv_bfloat162 h = __floats2bfloat162_rn(x, y);
    __nv_bfloat162 l = __floats2bfloat162_rn(x - __bfloat162float(h.x),
                                             y - __bfloat162float(h.y));
    hi = *reinterpret_cast<const unsigned*>(&h);
    lo = *reinterpret_cast<const unsigned*>(&l);
}

// ===========================================================================
// HMMA GEMM, bf16-plane operands: C[M,N] = (Ah+Al)[M,K] @ (Bh+Bl)[N,K]^T.
// 3-MMA split (hh + hl + lh), fp32 accumulators. CTA tile 128x256, 8 warps
// (2x4, 64x64 each), SW64 swizzle. 4-buffer cp.async ring consumed TWO 32-K
// chunks per barrier (one wait_group 0 + one __syncthreads per 64-K), and
// same-accumulator MMAs are term-batched 8 apart to break RAW chains.
// Requires M%128==0, N%256==0, K%64==0, K/32 >= 4.
// ===========================================================================
// Per stage: Ahi 8K @0, Alo 8K @8192, Bhi 16K @16384, Blo 16K @32768
#define STG_BYTES 49152
#define STAGES    4
#define SMEM_TOTAL (STAGES * STG_BYTES)   // 192 KB

extern __shared__ __align__(1024) char dynsmem[];

template<bool WRITE_F32, bool WRITE_HILO>
__global__ void __launch_bounds__(256, 1)
tc_gemm(const bf16* __restrict__ Ah, const bf16* __restrict__ Al,
        int lda, long long sA,
        const bf16* __restrict__ Bh, const bf16* __restrict__ Bl,
        int ldb, long long sB,
        float* __restrict__ C, bf16* __restrict__ Ch, bf16* __restrict__ Cl,
        int ldc, long long sC,
        int K, const float* __restrict__ bias)
{
    const uint32_t sbase = smem_to_u32(dynsmem);
    const int tid = threadIdx.x;
    const int wid = tid >> 5;
    const int lid = tid & 31;
    const int warpM = (wid >> 2) * 64;           // 0 or 64 (rows)
    const int warpNc = (wid & 3) * 64;           // 0..192 (cols)
    const uint32_t aWarp = (uint32_t)((wid >> 2) * 4096);  // 64 rows * 64B
    const uint32_t bWarp = (uint32_t)((wid & 3) * 4096);   // 64 rows * 64B

    const long long zA = (long long)blockIdx.z * sA + (long long)blockIdx.y * 128 * lda;
    const long long zB = (long long)blockIdx.z * sB + (long long)blockIdx.x * 256 * ldb;
    const bf16* Ahb = Ah + zA;
    const bf16* Alb = Al + zA;
    const bf16* Bhb = Bh + zB;
    const bf16* Blb = Bl + zB;

    // ---- producer: cp.async one 32-K chunk into ring buffer kts&3 ----
    const int pr   = tid >> 2;           // 0..63 row base
    const int pc16 = (tid & 3) * 16;     // byte chunk within 64B row
    auto issue_stage = [&](int kts) {
        const int k0 = kts << 5;         // elements
        const uint32_t buf = sbase + (uint32_t)(kts & (STAGES - 1)) * STG_BYTES;
        const uint32_t off0 = (uint32_t)(pr * 64 + pc16);
#pragma unroll
        for (int i = 0; i < 2; i++) {    // A planes: 128 rows
            const int row = i * 64 + pr;
            const uint32_t off = off0 + (uint32_t)(i * 4096);
            const uint32_t sw  = off ^ ((off >> 3) & 0x30u);
            cp_async16(buf +        sw, (const char*)(Ahb + (long long)row * lda + k0) + pc16);
            cp_async16(buf + 8192 + sw, (const char*)(Alb + (long long)row * lda + k0) + pc16);
        }
#pragma unroll
        for (int i = 0; i < 4; i++) {    // B planes: 256 rows
            const int row = i * 64 + pr;
            const uint32_t off = off0 + (uint32_t)(i * 4096);
            const uint32_t sw  = off ^ ((off >> 3) & 0x30u);
            cp_async16(buf + 16384 + sw, (const char*)(Bhb + (long long)row * ldb + k0) + pc16);
            cp_async16(buf + 32768 + sw, (const char*)(Blb + (long long)row * ldb + k0) + pc16);
        }
    };

    // ---- consumer lane addressing (bench-verified R7-R10) ----
    const uint32_t aOff = (uint32_t)((lid & 7) * 64 + ((lid >> 3) & 1) * 512 + (lid >> 4) * 16);
    const uint32_t aMsk = (aOff >> 3) & 0x30u;
    const uint32_t aSw0 = aOff ^ aMsk;
    const uint32_t aSw1 = (aOff | 32u) ^ aMsk;
    const uint32_t bOff = (uint32_t)((lid & 7) * 64 + ((lid >> 4) & 1) * 512 + ((lid >> 3) & 1) * 16);
    const uint32_t bMsk = (bOff >> 3) & 0x30u;
    const uint32_t bSw0 = bOff ^ bMsk;
    const uint32_t bSw1 = (bOff | 32u) ^ bMsk;

    float acc[4][8][4];
#pragma unroll
    for (int i = 0; i < 4; i++)
#pragma unroll
        for (int j = 0; j < 8; j++)
#pragma unroll
            for (int k = 0; k < 4; k++) acc[i][j][k] = 0.0f;

    const int T = K >> 5;                // even by contract

    // ---- consume one 32-K chunk (buffer kt&3); term-batched MMA order ----
    auto consume_chunk = [&](int kt) {
        const uint32_t stb = sbase + (uint32_t)(kt & (STAGES - 1)) * STG_BYTES;
#pragma unroll
        for (int ks = 0; ks < 2; ks++) {
            const uint32_t asw = ks ? aSw1 : aSw0;
            const uint32_t bsw = ks ? bSw1 : bSw0;

            uint32_t ah[4][4], al[4][4];
#pragma unroll
            for (int mb = 0; mb < 4; mb++) {
                const uint32_t ad = stb + aWarp + (uint32_t)(mb * 1024) + asw;
                ldmatrix_x4(ah[mb], ad);
                ldmatrix_x4(al[mb], ad + 8192u);
            }
#pragma unroll
            for (int p = 0; p < 4; p++) {        // 16 N-rows per p
                uint32_t bh4[4], bl4[4];
                const uint32_t bd = stb + 16384u + bWarp + (uint32_t)(p * 1024) + bsw;
                ldmatrix_x4(bh4, bd);
                ldmatrix_x4(bl4, bd + 16384u);
                // term-batched: same-accumulator MMAs spaced 8 apart
#pragma unroll
                for (int mb = 0; mb < 4; mb++)
#pragma unroll
                    for (int q = 0; q < 2; q++)
                        mma_bf16(acc[mb][p * 2 + q], ah[mb], &bh4[q * 2]); // hi*hi
#pragma unroll
                for (int mb = 0; mb < 4; mb++)
#pragma unroll
                    for (int q = 0; q < 2; q++)
                        mma_bf16(acc[mb][p * 2 + q], ah[mb], &bl4[q * 2]); // hi*lo
#pragma unroll
                for (int mb = 0; mb < 4; mb++)
#pragma unroll
                    for (int q = 0; q < 2; q++)
                        mma_bf16(acc[mb][p * 2 + q], al[mb], &bh4[q * 2]); // lo*hi
            }
        }
    };

    // ---- prologue: chunks 0,1 in flight (one group) ----
    issue_stage(0);
    issue_stage(1);
    CP_COMMIT();

    // ---- main pipeline: one barrier per 64-K (two chunks) ----
    for (int kt = 0; kt < T; kt += 2) {
        CP_WAIT0();                      // chunks kt, kt+1 landed
        __syncthreads();                 // all warps done reading kt-2, kt-1
        if (kt + 2 < T) {                // refill the two buffers just freed
            issue_stage(kt + 2);
            issue_stage(kt + 3);
        }
        CP_COMMIT();
        consume_chunk(kt);
        consume_chunk(kt + 1);
    }

    // ---- epilogue ----
    const long long cbase = (long long)blockIdx.z * sC
                          + (long long)blockIdx.y * 128 * ldc + blockIdx.x * 256;
#pragma unroll
    for (int mb = 0; mb < 4; mb++) {
        const int r0 = warpM + mb * 16 + (lid >> 2);
#pragma unroll
        for (int nb = 0; nb < 8; nb++) {
            const int c0 = warpNc + nb * 8 + (lid & 3) * 2;
            float b0 = 0.0f, b1 = 0.0f;
            if (bias) {
                const float* bp = bias + blockIdx.x * 256 + c0;
                b0 = bp[0]; b1 = bp[1];
            }
            const float v00 = acc[mb][nb][0] + b0, v01 = acc[mb][nb][1] + b1;
            const float v10 = acc[mb][nb][2] + b0, v11 = acc[mb][nb][3] + b1;
            const long long o0 = cbase + (long long)r0 * ldc + c0;
            const long long o1 = o0 + (long long)8 * ldc;
            if (WRITE_F32) {
                *(float2*)(C + o0) = make_float2(v00, v01);
                *(float2*)(C + o1) = make_float2(v10, v11);
            }
            if (WRITE_HILO) {
                uint32_t h, l;
                split2(v00, v01, h, l);
                *(uint32_t*)(Ch + o0) = h;
                *(uint32_t*)(Cl + o0) = l;
                split2(v10, v11, h, l);
                *(uint32_t*)(Ch + o1) = h;
                *(uint32_t*)(Cl + o1) = l;
            }
        }
    }
}

// ===========================================================================
// fp32 -> bf16 hi/lo plane split (for X, W_in, W_out). 4 elems/thread.
// ===========================================================================
__global__ __launch_bounds__(256)
void split_f32(const float* __restrict__ x, bf16* __restrict__ hi,
               bf16* __restrict__ lo, long long n4)
{
    const long long i = (long long)blockIdx.x * 256 + threadIdx.x;
    if (i >= n4) return;
    const float4 v = ((const float4*)x)[i];
    uint32_t h0, l0, h1, l1;
    split2(v.x, v.y, h0, l0);
    split2(v.z, v.w, h1, l1);
    ((uint2*)hi)[i] = make_uint2(h0, h1);
    ((uint2*)lo)[i] = make_uint2(l0, l1);
}

// ===========================================================================
// V transpose on hi/lo planes: vt[b][d][s] = V[b][s][d]; hi,lo packed u32.
// ===========================================================================
__global__ __launch_bounds__(256)
void transpose_v(const bf16* __restrict__ qh, const bf16* __restrict__ ql,
                 bf16* __restrict__ vth, bf16* __restrict__ vtl)
{
    __shared__ uint32_t t[32][33];
    const int s0 = blockIdx.x * 32;
    const int d0 = blockIdx.y * 32;
    const int b  = blockIdx.z;
    const int tx = threadIdx.x, ty = threadIdx.y;

    const long long vb = (long long)b * SEQ * 3 * HDIM + 2 * HDIM;
#pragma unroll
    for (int j = 0; j < 4; j++) {
        const long long idx = vb + (long long)(s0 + ty + j * 8) * (3 * HDIM) + d0 + tx;
        const uint32_t h = *(const unsigned short*)(qh + idx);
        const uint32_t l = *(const unsigned short*)(ql + idx);
        t[ty + j * 8][tx] = h | (l << 16);
    }
    __syncthreads();

    const long long ob = (long long)b * HDIM * SEQ;
#pragma unroll
    for (int j = 0; j < 4; j++) {
        const long long idx = ob + (long long)(d0 + ty + j * 8) * SEQ + s0 + tx;
        const uint32_t v = t[tx][ty + j * 8];
        *(unsigned short*)(vth + idx) = (unsigned short)(v & 0xffffu);
        *(unsigned short*)(vtl + idx) = (unsigned short)(v >> 16);
    }
}

// ===========================================================================
// Softmax: reads fp32 scores + mask (applied BEFORE /sqrt(DIM)), writes
// attn probability hi/lo bf16 planes.
// ===========================================================================
__global__ __launch_bounds__(256)
void softmax_kernel(const float* __restrict__ scores, const int* __restrict__ mask,
                    bf16* __restrict__ ah, bf16* __restrict__ al)
{
    const long long row = blockIdx.x;
    const int b = (int)(row / SEQ);
    const float* p = scores + row * SEQ;
    const int* mrow = mask + (long long)b * SEQ;
    const int t = threadIdx.x;

    float v[8];
    float mx = -3.402823466e38f;
#pragma unroll
    for (int j = 0; j < 8; j++) {
        int c = t + j * 256;
        float s = p[c];
        if (mrow[c] == 0) s = -1e20f;
        s *= 0.03125f;                 // 1/sqrt(1024)
        v[j] = s;
        mx = fmaxf(mx, s);
    }

    __shared__ float redmax[8];
    __shared__ float redsum[8];

#pragma unroll
    for (int o = 16; o > 0; o >>= 1)
        mx = fmaxf(mx, __shfl_xor_sync(0xffffffffu, mx, o));
    if ((t & 31) == 0) redmax[t >> 5] = mx;
    __syncthreads();
    mx = redmax[0];
#pragma unroll
    for (int w = 1; w < 8; w++) mx = fmaxf(mx, redmax[w]);

    float sum = 0.0f;
#pragma unroll
    for (int j = 0; j < 8; j++) {
        v[j] = __expf(v[j] - mx);
        sum += v[j];
    }
#pragma unroll
    for (int o = 16; o > 0; o >>= 1)
        sum += __shfl_xor_sync(0xffffffffu, sum, o);
    if ((t & 31) == 0) redsum[t >> 5] = sum;
    __syncthreads();
    sum = 0.0f;
#pragma unroll
    for (int w = 0; w < 8; w++) sum += redsum[w];

    const float inv = 1.0f / sum;
    bf16* ph = ah + row * SEQ;
    bf16* pl = al + row * SEQ;
#pragma unroll
    for (int j = 0; j < 8; j++) {
        const int c = t + j * 256;
        const float r = v[j] * inv;
        const bf16 h = __float2bfloat16_rn(r);
        ph[c] = h;
        pl[c] = __float2bfloat16_rn(r - __bfloat162float(h));
    }
}

// ===========================================================================
// Launch
// ===========================================================================
extern "C" void kernel_launch(void* const* d_in, const int* in_sizes, int n_in,
                              void* d_out, int out_size)
{
    const float* X     = (const float*)d_in[0];
    const int*   mask  = (const int*)  d_in[1];
    const float* W_in  = (const float*)d_in[2];
    const float* b_in  = (const float*)d_in[3];
    const float* W_out = (const float*)d_in[4];
    const float* b_out = (const float*)d_in[5];
    float*       Y     = (float*)d_out;

    bf16 *xh, *xl, *wih, *wil, *woh, *wol, *qh, *ql, *ath, *atl, *vth, *vtl, *ch, *cl;
    float* sc;
    cudaGetSymbolAddress((void**)&xh,  g_x_hi);
    cudaGetSymbolAddress((void**)&xl,  g_x_lo);
    cudaGetSymbolAddress((void**)&wih, g_win_hi);
    cudaGetSymbolAddress((void**)&wil, g_win_lo);
    cudaGetSymbolAddress((void**)&woh, g_wout_hi);
    cudaGetSymbolAddress((void**)&wol, g_wout_lo);
    cudaGetSymbolAddress((void**)&qh,  g_qkv_hi);
    cudaGetSymbolAddress((void**)&ql,  g_qkv_lo);
    cudaGetSymbolAddress((void**)&sc,  g_scores);
    cudaGetSymbolAddress((void**)&ath, g_attn_hi);
    cudaGetSymbolAddress((void**)&atl, g_attn_lo);
    cudaGetSymbolAddress((void**)&vth, g_vt_hi);
    cudaGetSymbolAddress((void**)&vtl, g_vt_lo);
    cudaGetSymbolAddress((void**)&ch,  g_ctx_hi);
    cudaGetSymbolAddress((void**)&cl,  g_ctx_lo);

    cudaFuncSetAttribute(tc_gemm<false, true>,
                         cudaFuncAttributeMaxDynamicSharedMemorySize, SMEM_TOTAL);
    cudaFuncSetAttribute(tc_gemm<true, false>,
                         cudaFuncAttributeMaxDynamicSharedMemorySize, SMEM_TOTAL);

    dim3 blk(256);

    // 0. operand splits
    split_f32<<<(unsigned)((size_t)MTOT * HDIM / 4 / 256), blk>>>(X, xh, xl,
        (long long)MTOT * HDIM / 4);
    split_f32<<<(unsigned)((size_t)3 * HDIM * HDIM / 4 / 256), blk>>>(W_in, wih, wil,
        (long long)3 * HDIM * HDIM / 4);
    split_f32<<<(unsigned)((size_t)HDIM * HDIM / 4 / 256), blk>>>(W_out, woh, wol,
        (long long)HDIM * HDIM / 4);

    // 1. qkv = X @ W_in^T + b_in  -> hi/lo planes   [8192,3072], K=1024
    tc_gemm<false, true><<<dim3(12, 64, 1), blk, SMEM_TOTAL>>>(
        xh, xl, HDIM, 0,
        wih, wil, HDIM, 0,
        nullptr, qh, ql, 3 * HDIM, 0,
        HDIM, b_in);

    // 2. V^T planes
    transpose_v<<<dim3(SEQ / 32, HDIM / 32, B_BATCH), dim3(32, 8)>>>(qh, ql, vth, vtl);

    // 3. scores[b] = Q[b] @ K[b]^T -> fp32   [2048,2048] x4, K=1024
    tc_gemm<true, false><<<dim3(8, 16, B_BATCH), blk, SMEM_TOTAL>>>(
        qh,        ql,        3 * HDIM, (long long)SEQ * 3 * HDIM,
        qh + HDIM, ql + HDIM, 3 * HDIM, (long long)SEQ * 3 * HDIM,
        sc, nullptr, nullptr, SEQ, (long long)SEQ * SEQ,
        HDIM, nullptr);

    // 4. softmax -> attn hi/lo planes
    softmax_kernel<<<B_BATCH * SEQ, blk>>>(sc, mask, ath, atl);

    // 5. ctx[b] = attn[b] @ (V^T[b])^T -> hi/lo planes   [2048,1024] x4, K=2048
    tc_gemm<false, true><<<dim3(4, 16, B_BATCH), blk, SMEM_TOTAL>>>(
        ath, atl, SEQ, (long long)SEQ * SEQ,
        vth, vtl, SEQ, (long long)HDIM * SEQ,
        nullptr, ch, cl, HDIM, (long long)SEQ * HDIM,
        SEQ, nullptr);

    // 6. Y = ctx @ W_out^T + b_out -> fp32   [8192,1024], K=1024
    tc_gemm<true, false><<<dim3(4, 64, 1), blk, SMEM_TOTAL>>>(
        ch, cl, HDIM, 0,
        woh, wol, HDIM, 0,
        Y, nullptr, nullptr, HDIM, 0,
        HDIM, b_out);
}

// round 16
// speedup vs baseline: 1.1894x; 1.1009x over previous
#include <cuda_runtime.h>
#include <cuda_bf16.h>
#include <cstdint>

#define B_BATCH 4
#define SEQ     2048
#define HDIM    1024
#define MTOT    (B_BATCH * SEQ)

typedef __nv_bfloat16 bf16;

// ---------------------------------------------------------------------------
// Scratch (allocation-free rule: __device__ globals). All GEMM operands live
// as bf16 hi/lo planes (hi = rn(x), lo = rn(x - hi)): same bytes as fp32.
// ---------------------------------------------------------------------------
__device__ bf16  g_x_hi   [(size_t)MTOT * HDIM];
__device__ bf16  g_x_lo   [(size_t)MTOT * HDIM];
__device__ bf16  g_win_hi [(size_t)3 * HDIM * HDIM];
__device__ bf16  g_win_lo [(size_t)3 * HDIM * HDIM];
__device__ bf16  g_wout_hi[(size_t)HDIM * HDIM];
__device__ bf16  g_wout_lo[(size_t)HDIM * HDIM];
__device__ bf16  g_qkv_hi [(size_t)MTOT * 3 * HDIM];
__device__ bf16  g_qkv_lo [(size_t)MTOT * 3 * HDIM];
__device__ float g_scores [(size_t)B_BATCH * SEQ * SEQ];
__device__ bf16  g_attn_hi[(size_t)B_BATCH * SEQ * SEQ];
__device__ bf16  g_attn_lo[(size_t)B_BATCH * SEQ * SEQ];
__device__ bf16  g_vt_hi  [(size_t)B_BATCH * HDIM * SEQ];
__device__ bf16  g_vt_lo  [(size_t)B_BATCH * HDIM * SEQ];
__device__ bf16  g_ctx_hi [(size_t)MTOT * HDIM];
__device__ bf16  g_ctx_lo [(size_t)MTOT * HDIM];

// ===========================================================================
// Base-ISA primitives (compute_103-safe): ldmatrix + mma.sync + cp.async
// ===========================================================================
__device__ __forceinline__ uint32_t smem_to_u32(const void* p) {
    uint32_t a;
    asm("{ .reg .u64 t; cvta.to.shared.u64 t, %1; cvt.u32.u64 %0, t; }"
        : "=r"(a) : "l"(p));
    return a;
}

__device__ __forceinline__ void ldmatrix_x4(uint32_t* r, uint32_t addr) {
    asm volatile("ldmatrix.sync.aligned.m8n8.x4.shared.b16 {%0,%1,%2,%3}, [%4];"
        : "=r"(r[0]), "=r"(r[1]), "=r"(r[2]), "=r"(r[3]) : "r"(addr));
}

__device__ __forceinline__ void mma_bf16(float* c, const uint32_t* a,
                                         const uint32_t* b) {
    asm volatile(
        "mma.sync.aligned.m16n8k16.row.col.f32.bf16.bf16.f32 "
        "{%0,%1,%2,%3}, {%4,%5,%6,%7}, {%8,%9}, {%0,%1,%2,%3};"
        : "+f"(c[0]), "+f"(c[1]), "+f"(c[2]), "+f"(c[3])
        : "r"(a[0]), "r"(a[1]), "r"(a[2]), "r"(a[3]), "r"(b[0]), "r"(b[1]));
}

__device__ __forceinline__ void cp_async16(uint32_t dst, const void* src) {
    asm volatile("cp.async.cg.shared.global [%0], [%1], 16;"
        :: "r"(dst), "l"(src) : "memory");
}
#define CP_COMMIT() asm volatile("cp.async.commit_group;" ::: "memory")
#define CP_WAIT1()  asm volatile("cp.async.wait_group 1;"  ::: "memory")
#define CP_WAIT0()  asm volatile("cp.async.wait_group 0;"  ::: "memory")

__device__ __forceinline__ void split2(float x, float y, uint32_t& hi, uint32_t& lo) {
    __nv_bfloat162 h = __floats2bfloat162_rn(x, y);
    __nv_bfloat162 l = __floats2bfloat162_rn(x - __bfloat162float(h.x),
                                             y - __bfloat162float(h.y));
    hi = *reinterpret_cast<const unsigned*>(&h);
    lo = *reinterpret_cast<const unsigned*>(&l);
}

// ===========================================================================
// HMMA GEMM, bf16-plane operands: C[M,N] = (Ah+Al)[M,K] @ (Bh+Bl)[N,K]^T.
// 3-MMA split (hh + hl + lh), fp32 accumulators.
// CTA tile 128x128, 128 THREADS (4 warps, 2x2, 64x64 each) so that TWO CTAs
// co-reside per SM (2x128x256regs = full RF): 4 warps/SMSP from independent
// CTAs cover each other's LDSM/barrier stalls. 3-stage cp.async ring (96 KB),
// SW64 swizzle. Per 16-K step: all 16 LDSMs up front, then 48 MMAs
// term-batched (same-acc spaced 8 apart). Requires M%128==0, N%128==0,
// K%32==0, K/32 >= 3.
// ===========================================================================
// Per stage: Ahi 8K @0, Alo 8K @8192, Bhi 8K @16384, Blo 8K @24576
#define STG_BYTES 32768
#define STAGES    3
#define SMEM_TOTAL (STAGES * STG_BYTES)   // 96 KB
#define NTHREADS  128

extern __shared__ __align__(1024) char dynsmem[];

template<bool WRITE_F32, bool WRITE_HILO>
__global__ void __launch_bounds__(NTHREADS, 2)
tc_gemm(const bf16* __restrict__ Ah, const bf16* __restrict__ Al,
        int lda, long long sA,
        const bf16* __restrict__ Bh, const bf16* __restrict__ Bl,
        int ldb, long long sB,
        float* __restrict__ C, bf16* __restrict__ Ch, bf16* __restrict__ Cl,
        int ldc, long long sC,
        int K, const float* __restrict__ bias)
{
    const uint32_t sbase = smem_to_u32(dynsmem);
    const int tid = threadIdx.x;
    const int wid = tid >> 5;
    const int lid = tid & 31;
    const int warpM = (wid >> 1) * 64;           // 0 or 64 (rows)
    const int warpNc = (wid & 1) * 64;           // 0 or 64 (cols)
    const uint32_t aWarp = (uint32_t)((wid >> 1) * 4096);  // 64 rows * 64B
    const uint32_t bWarp = (uint32_t)((wid & 1) * 4096);   // 64 rows * 64B

    const long long zA = (long long)blockIdx.z * sA + (long long)blockIdx.y * 128 * lda;
    const long long zB = (long long)blockIdx.z * sB + (long long)blockIdx.x * 128 * ldb;
    const bf16* Ahb = Ah + zA;
    const bf16* Alb = Al + zA;
    const bf16* Bhb = Bh + zB;
    const bf16* Blb = Bl + zB;

    // ---- producer: cp.async one 32-K chunk (4 planes x 128 rows) ----
    const int pr   = tid >> 2;           // 0..31 row base
    const int pc16 = (tid & 3) * 16;     // byte chunk within 64B row
    auto issue_stage = [&](int kts) {
        const int k0 = kts << 5;         // elements
        const uint32_t buf = sbase + (uint32_t)(kts % STAGES) * STG_BYTES;
        const uint32_t off0 = (uint32_t)(pr * 64 + pc16);
#pragma unroll
        for (int i = 0; i < 4; i++) {    // 4 x 32 rows = 128 rows per plane
            const int row = i * 32 + pr;
            const uint32_t off = off0 + (uint32_t)(i * 2048);
            const uint32_t sw  = off ^ ((off >> 3) & 0x30u);
            cp_async16(buf +         sw, (const char*)(Ahb + (long long)row * lda + k0) + pc16);
            cp_async16(buf +  8192 + sw, (const char*)(Alb + (long long)row * lda + k0) + pc16);
            cp_async16(buf + 16384 + sw, (const char*)(Bhb + (long long)row * ldb + k0) + pc16);
            cp_async16(buf + 24576 + sw, (const char*)(Blb + (long long)row * ldb + k0) + pc16);
        }
    };

    // ---- consumer lane addressing (bench-verified R7-R12) ----
    const uint32_t aOff = (uint32_t)((lid & 7) * 64 + ((lid >> 3) & 1) * 512 + (lid >> 4) * 16);
    const uint32_t aMsk = (aOff >> 3) & 0x30u;
    const uint32_t aSw0 = aOff ^ aMsk;
    const uint32_t aSw1 = (aOff | 32u) ^ aMsk;
    const uint32_t bOff = (uint32_t)((lid & 7) * 64 + ((lid >> 4) & 1) * 512 + ((lid >> 3) & 1) * 16);
    const uint32_t bMsk = (bOff >> 3) & 0x30u;
    const uint32_t bSw0 = bOff ^ bMsk;
    const uint32_t bSw1 = (bOff | 32u) ^ bMsk;

    float acc[4][8][4];
#pragma unroll
    for (int i = 0; i < 4; i++)
#pragma unroll
        for (int j = 0; j < 8; j++)
#pragma unroll
            for (int k = 0; k < 4; k++) acc[i][j][k] = 0.0f;

    const int T = K >> 5;

    // ---- consume one 32-K chunk from buffer kt%3 ----
    auto consume_chunk = [&](int kt) {
        const uint32_t stb = sbase + (uint32_t)(kt % STAGES) * STG_BYTES;
#pragma unroll
        for (int ks = 0; ks < 2; ks++) {
            const uint32_t asw = ks ? aSw1 : aSw0;
            const uint32_t bsw = ks ? bSw1 : bSw0;

            // all 16 LDSMs up front: no loads interleaved with MMAs
            uint32_t ah[4][4], al[4][4], bh[4][4], bl[4][4];
#pragma unroll
            for (int mb = 0; mb < 4; mb++) {
                const uint32_t ad = stb + aWarp + (uint32_t)(mb * 1024) + asw;
                ldmatrix_x4(ah[mb], ad);
                ldmatrix_x4(al[mb], ad + 8192u);
            }
#pragma unroll
            for (int p = 0; p < 4; p++) {
                const uint32_t bd = stb + 16384u + bWarp + (uint32_t)(p * 1024) + bsw;
                ldmatrix_x4(bh[p], bd);
                ldmatrix_x4(bl[p], bd + 8192u);
            }
            // 48 MMAs, term-batched (same-accumulator spaced 16 apart)
#pragma unroll
            for (int mb = 0; mb < 4; mb++)
#pragma unroll
                for (int p = 0; p < 4; p++)
#pragma unroll
                    for (int q = 0; q < 2; q++)
                        mma_bf16(acc[mb][p * 2 + q], ah[mb], &bh[p][q * 2]); // hi*hi
#pragma unroll
            for (int mb = 0; mb < 4; mb++)
#pragma unroll
                for (int p = 0; p < 4; p++)
#pragma unroll
                    for (int q = 0; q < 2; q++)
                        mma_bf16(acc[mb][p * 2 + q], ah[mb], &bl[p][q * 2]); // hi*lo
#pragma unroll
            for (int mb = 0; mb < 4; mb++)
#pragma unroll
                for (int p = 0; p < 4; p++)
#pragma unroll
                    for (int q = 0; q < 2; q++)
                        mma_bf16(acc[mb][p * 2 + q], al[mb], &bh[p][q * 2]); // lo*hi
        }
    };

    // ---- prologue: chunks 0,1 in flight (one group each) ----
    issue_stage(0); CP_COMMIT();
    issue_stage(1); CP_COMMIT();

    // ---- main pipeline: 3-stage ring, one barrier per chunk ----
    // iter kt: pending={kt,kt+1}; wait1 -> kt landed; sync frees buffer
    // (kt+2)%3 (read as chunk kt-1 last iter); issue kt+2; consume kt.
    // Last iter (kt==T-1): pending={T-1}; wait1 would NOT guarantee
    // completion -> use wait0 there.
    for (int kt = 0; kt < T; kt++) {
        if (kt + 1 < T) { CP_WAIT1(); } else { CP_WAIT0(); }
        __syncthreads();
        if (kt + 2 < T) { issue_stage(kt + 2); CP_COMMIT(); }
        consume_chunk(kt);
    }

    // ---- epilogue ----
    const long long cbase = (long long)blockIdx.z * sC
                          + (long long)blockIdx.y * 128 * ldc + blockIdx.x * 128;
#pragma unroll
    for (int mb = 0; mb < 4; mb++) {
        const int r0 = warpM + mb * 16 + (lid >> 2);
#pragma unroll
        for (int nb = 0; nb < 8; nb++) {
            const int c0 = warpNc + nb * 8 + (lid & 3) * 2;
            float b0 = 0.0f, b1 = 0.0f;
            if (bias) {
                const float* bp = bias + blockIdx.x * 128 + c0;
                b0 = bp[0]; b1 = bp[1];
            }
            const float v00 = acc[mb][nb][0] + b0, v01 = acc[mb][nb][1] + b1;
            const float v10 = acc[mb][nb][2] + b0, v11 = acc[mb][nb][3] + b1;
            const long long o0 = cbase + (long long)r0 * ldc + c0;
            const long long o1 = o0 + (long long)8 * ldc;
            if (WRITE_F32) {
                *(float2*)(C + o0) = make_float2(v00, v01);
                *(float2*)(C + o1) = make_float2(v10, v11);
            }
            if (WRITE_HILO) {
                uint32_t h, l;
                split2(v00, v01, h, l);
                *(uint32_t*)(Ch + o0) = h;
                *(uint32_t*)(Cl + o0) = l;
                split2(v10, v11, h, l);
                *(uint32_t*)(Ch + o1) = h;
                *(uint32_t*)(Cl + o1) = l;
            }
        }
    }
}

// ===========================================================================
// fp32 -> bf16 hi/lo plane split (for X, W_in, W_out). 4 elems/thread.
// ===========================================================================
__global__ __launch_bounds__(256)
void split_f32(const float* __restrict__ x, bf16* __restrict__ hi,
               bf16* __restrict__ lo, long long n4)
{
    const long long i = (long long)blockIdx.x * 256 + threadIdx.x;
    if (i >= n4) return;
    const float4 v = ((const float4*)x)[i];
    uint32_t h0, l0, h1, l1;
    split2(v.x, v.y, h0, l0);
    split2(v.z, v.w, h1, l1);
    ((uint2*)hi)[i] = make_uint2(h0, h1);
    ((uint2*)lo)[i] = make_uint2(l0, l1);
}

// ===========================================================================
// V transpose on hi/lo planes: vt[b][d][s] = V[b][s][d]; hi,lo packed u32.
// ===========================================================================
__global__ __launch_bounds__(256)
void transpose_v(const bf16* __restrict__ qh, const bf16* __restrict__ ql,
                 bf16* __restrict__ vth, bf16* __restrict__ vtl)
{
    __shared__ uint32_t t[32][33];
    const int s0 = blockIdx.x * 32;
    const int d0 = blockIdx.y * 32;
    const int b  = blockIdx.z;
    const int tx = threadIdx.x, ty = threadIdx.y;

    const long long vb = (long long)b * SEQ * 3 * HDIM + 2 * HDIM;
#pragma unroll
    for (int j = 0; j < 4; j++) {
        const long long idx = vb + (long long)(s0 + ty + j * 8) * (3 * HDIM) + d0 + tx;
        const uint32_t h = *(const unsigned short*)(qh + idx);
        const uint32_t l = *(const unsigned short*)(ql + idx);
        t[ty + j * 8][tx] = h | (l << 16);
    }
    __syncthreads();

    const long long ob = (long long)b * HDIM * SEQ;
#pragma unroll
    for (int j = 0; j < 4; j++) {
        const long long idx = ob + (long long)(d0 + ty + j * 8) * SEQ + s0 + tx;
        const uint32_t v = t[tx][ty + j * 8];
        *(unsigned short*)(vth + idx) = (unsigned short)(v & 0xffffu);
        *(unsigned short*)(vtl + idx) = (unsigned short)(v >> 16);
    }
}

// ===========================================================================
// Softmax: reads fp32 scores + mask (applied BEFORE /sqrt(DIM)), writes
// attn probability hi/lo bf16 planes.
// ===========================================================================
__global__ __launch_bounds__(256)
void softmax_kernel(const float* __restrict__ scores, const int* __restrict__ mask,
                    bf16* __restrict__ ah, bf16* __restrict__ al)
{
    const long long row = blockIdx.x;
    const int b = (int)(row / SEQ);
    const float* p = scores + row * SEQ;
    const int* mrow = mask + (long long)b * SEQ;
    const int t = threadIdx.x;

    float v[8];
    float mx = -3.402823466e38f;
#pragma unroll
    for (int j = 0; j < 8; j++) {
        int c = t + j * 256;
        float s = p[c];
        if (mrow[c] == 0) s = -1e20f;
        s *= 0.03125f;                 // 1/sqrt(1024)
        v[j] = s;
        mx = fmaxf(mx, s);
    }

    __shared__ float redmax[8];
    __shared__ float redsum[8];

#pragma unroll
    for (int o = 16; o > 0; o >>= 1)
        mx = fmaxf(mx, __shfl_xor_sync(0xffffffffu, mx, o));
    if ((t & 31) == 0) redmax[t >> 5] = mx;
    __syncthreads();
    mx = redmax[0];
#pragma unroll
    for (int w = 1; w < 8; w++) mx = fmaxf(mx, redmax[w]);

    float sum = 0.0f;
#pragma unroll
    for (int j = 0; j < 8; j++) {
        v[j] = __expf(v[j] - mx);
        sum += v[j];
    }
#pragma unroll
    for (int o = 16; o > 0; o >>= 1)
        sum += __shfl_xor_sync(0xffffffffu, sum, o);
    if ((t & 31) == 0) redsum[t >> 5] = sum;
    __syncthreads();
    sum = 0.0f;
#pragma unroll
    for (int w = 0; w < 8; w++) sum += redsum[w];

    const float inv = 1.0f / sum;
    bf16* ph = ah + row * SEQ;
    bf16* pl = al + row * SEQ;
#pragma unroll
    for (int j = 0; j < 8; j++) {
        const int c = t + j * 256;
        const float r = v[j] * inv;
        const bf16 h = __float2bfloat16_rn(r);
        ph[c] = h;
        pl[c] = __float2bfloat16_rn(r - __bfloat162float(h));
    }
}

// ===========================================================================
// Launch
// ===========================================================================
extern "C" void kernel_launch(void* const* d_in, const int* in_sizes, int n_in,
                              void* d_out, int out_size)
{
    const float* X     = (const float*)d_in[0];
    const int*   mask  = (const int*)  d_in[1];
    const float* W_in  = (const float*)d_in[2];
    const float* b_in  = (const float*)d_in[3];
    const float* W_out = (const float*)d_in[4];
    const float* b_out = (const float*)d_in[5];
    float*       Y     = (float*)d_out;

    bf16 *xh, *xl, *wih, *wil, *woh, *wol, *qh, *ql, *ath, *atl, *vth, *vtl, *ch, *cl;
    float* sc;
    cudaGetSymbolAddress((void**)&xh,  g_x_hi);
    cudaGetSymbolAddress((void**)&xl,  g_x_lo);
    cudaGetSymbolAddress((void**)&wih, g_win_hi);
    cudaGetSymbolAddress((void**)&wil, g_win_lo);
    cudaGetSymbolAddress((void**)&woh, g_wout_hi);
    cudaGetSymbolAddress((void**)&wol, g_wout_lo);
    cudaGetSymbolAddress((void**)&qh,  g_qkv_hi);
    cudaGetSymbolAddress((void**)&ql,  g_qkv_lo);
    cudaGetSymbolAddress((void**)&sc,  g_scores);
    cudaGetSymbolAddress((void**)&ath, g_attn_hi);
    cudaGetSymbolAddress((void**)&atl, g_attn_lo);
    cudaGetSymbolAddress((void**)&vth, g_vt_hi);
    cudaGetSymbolAddress((void**)&vtl, g_vt_lo);
    cudaGetSymbolAddress((void**)&ch,  g_ctx_hi);
    cudaGetSymbolAddress((void**)&cl,  g_ctx_lo);

    cudaFuncSetAttribute(tc_gemm<false, true>,
                         cudaFuncAttributeMaxDynamicSharedMemorySize, SMEM_TOTAL);
    cudaFuncSetAttribute(tc_gemm<true, false>,
                         cudaFuncAttributeMaxDynamicSharedMemorySize, SMEM_TOTAL);

    dim3 blk(256);
    dim3 gblk(NTHREADS);

    // 0. operand splits
    split_f32<<<(unsigned)((size_t)MTOT * HDIM / 4 / 256), blk>>>(X, xh, xl,
        (long long)MTOT * HDIM / 4);
    split_f32<<<(unsigned)((size_t)3 * HDIM * HDIM / 4 / 256), blk>>>(W_in, wih, wil,
        (long long)3 * HDIM * HDIM / 4);
    split_f32<<<(unsigned)((size_t)HDIM * HDIM / 4 / 256), blk>>>(W_out, woh, wol,
        (long long)HDIM * HDIM / 4);

    // 1. qkv = X @ W_in^T + b_in  -> hi/lo planes   [8192,3072], K=1024
    tc_gemm<false, true><<<dim3(24, 64, 1), gblk, SMEM_TOTAL>>>(
        xh, xl, HDIM, 0,
        wih, wil, HDIM, 0,
        nullptr, qh, ql, 3 * HDIM, 0,
        HDIM, b_in);

    // 2. V^T planes
    transpose_v<<<dim3(SEQ / 32, HDIM / 32, B_BATCH), dim3(32, 8)>>>(qh, ql, vth, vtl);

    // 3. scores[b] = Q[b] @ K[b]^T -> fp32   [2048,2048] x4, K=1024
    tc_gemm<true, false><<<dim3(16, 16, B_BATCH), gblk, SMEM_TOTAL>>>(
        qh,        ql,        3 * HDIM, (long long)SEQ * 3 * HDIM,
        qh + HDIM, ql + HDIM, 3 * HDIM, (long long)SEQ * 3 * HDIM,
        sc, nullptr, nullptr, SEQ, (long long)SEQ * SEQ,
        HDIM, nullptr);

    // 4. softmax -> attn hi/lo planes
    softmax_kernel<<<B_BATCH * SEQ, blk>>>(sc, mask, ath, atl);

    // 5. ctx[b] = attn[b] @ (V^T[b])^T -> hi/lo planes   [2048,1024] x4, K=2048
    tc_gemm<false, true><<<dim3(8, 16, B_BATCH), gblk, SMEM_TOTAL>>>(
        ath, atl, SEQ, (long long)SEQ * SEQ,
        vth, vtl, SEQ, (long long)HDIM * SEQ,
        nullptr, ch, cl, HDIM, (long long)SEQ * HDIM,
        SEQ, nullptr);

    // 6. Y = ctx @ W_out^T + b_out -> fp32   [8192,1024], K=1024
    tc_gemm<true, false><<<dim3(8, 64, 1), gblk, SMEM_TOTAL>>>(
        ch, cl, HDIM, 0,
        woh, wol, HDIM, 0,
        Y, nullptr, nullptr, HDIM, 0,
        HDIM, b_out);
}